// round 6
// baseline (speedup 1.0000x reference)
#include <cuda_runtime.h>
#include <cstdint>

#define BB   2
#define HH   12
#define NN   2048
#define CC   768
#define DD   64

// Scratch (no allocations allowed)
__device__ float g_q[BB*HH*NN*DD];
__device__ float g_k[BB*HH*NN*DD];
__device__ float g_v[BB*HH*NN*DD];
__device__ float g_att[BB*NN*CC];
__device__ int   g_idx[BB*NN];
__device__ int   g_cnt[BB];

// ---------------------------------------------------------------------------
// mma.sync tf32 helpers
// ---------------------------------------------------------------------------
__device__ __forceinline__ void mma_tf32(float* d, const uint32_t* a,
                                         uint32_t b0, uint32_t b1)
{
    asm volatile(
        "mma.sync.aligned.m16n8k8.row.col.f32.tf32.tf32.f32 "
        "{%0,%1,%2,%3},{%4,%5,%6,%7},{%8,%9},{%0,%1,%2,%3};"
        : "+f"(d[0]), "+f"(d[1]), "+f"(d[2]), "+f"(d[3])
        : "r"(a[0]), "r"(a[1]), "r"(a[2]), "r"(a[3]), "r"(b0), "r"(b1));
}

__device__ __forceinline__ uint32_t to_tf32(float f)
{
    uint32_t u;
    asm("cvt.rna.tf32.f32 %0, %1;" : "=r"(u) : "f"(f));
    return u;
}

__device__ __forceinline__ void split_tf32(float v, uint32_t& hi, uint32_t& lo)
{
    hi = to_tf32(v);
    lo = to_tf32(v - __uint_as_float(hi));
}

// ---------------------------------------------------------------------------
// Compaction: per batch, gather indices of visible keys (mask == 0).
// ---------------------------------------------------------------------------
__global__ __launch_bounds__(1024) void compact_kernel(const float* __restrict__ mask)
{
    __shared__ int wsum[32];
    const int b = blockIdx.x;
    const int t = threadIdx.x;
    const int p0 = 2 * t, p1 = 2 * t + 1;
    const int v0 = (mask[b * NN + p0] == 0.0f) ? 1 : 0;
    const int v1 = (mask[b * NN + p1] == 0.0f) ? 1 : 0;
    const int s  = v0 + v1;

    int sc = s;
    #pragma unroll
    for (int o = 1; o < 32; o <<= 1) {
        int n = __shfl_up_sync(0xffffffffu, sc, o);
        if ((t & 31) >= o) sc += n;
    }
    if ((t & 31) == 31) wsum[t >> 5] = sc;
    __syncthreads();
    if (t < 32) {
        int w = wsum[t];
        #pragma unroll
        for (int o = 1; o < 32; o <<= 1) {
            int n = __shfl_up_sync(0xffffffffu, w, o);
            if (t >= o) w += n;
        }
        wsum[t] = w;
    }
    __syncthreads();
    const int excl = (sc - s) + ((t >= 32) ? wsum[(t >> 5) - 1] : 0);
    if (v0) g_idx[b * NN + excl] = p0;
    if (v1) g_idx[b * NN + excl + v0] = p1;
    if (t == 1023) g_cnt[b] = excl + s;
}

// ---------------------------------------------------------------------------
// Tensor-core GEMM, 3xTF32 split (fp32-equivalent accuracy).
// C[m,n] = sum_k A[m,k] * W[n,k]
// Block tile 128x128, k-step 16, double-buffered smem, 8 warps (64x32 each).
// MODE 0: Q proj -> g_q      MODE 1: K/V proj (compacted) -> g_k/g_v
// MODE 2: out proj (+bias) -> out
// ---------------------------------------------------------------------------
template<int MODE>
__global__ __launch_bounds__(256) void gemm_t(const float* __restrict__ A,
                                              const float* __restrict__ W,
                                              const float* __restrict__ bias,
                                              float* __restrict__ out)
{
    __shared__ __align__(16) float As[2][128][20];   // [m][k], pitch 20
    __shared__ __align__(16) float Bs[2][128][20];   // [n][k], pitch 20

    const int tid = threadIdx.x;
    const int n0 = blockIdx.x * 128;
    const int m0 = blockIdx.y * 128;
    int b = 0, cnt = 0;
    if (MODE == 1) {
        b = blockIdx.z;
        cnt = g_cnt[b];
        if (m0 >= cnt) return;
    }
    const float* Ap = (MODE == 2) ? g_att : A;

    // ---- global loader mapping: 2 float4 per array per thread ----
    int lrow[2], lcol[2];
    size_t a_off[2], b_off[2];
    #pragma unroll
    for (int p = 0; p < 2; p++) {
        const int f = tid + p * 256;          // 0..511
        lrow[p] = f >> 2;                     // 0..127
        lcol[p] = (f & 3) * 4;                // 0,4,8,12
        if (MODE == 1) {
            const int mrow = m0 + lrow[p];
            const int src  = (mrow < cnt) ? g_idx[b * NN + mrow] : 0;
            a_off[p] = ((size_t)(b * NN + src)) * CC + lcol[p];
        } else {
            a_off[p] = (size_t)(m0 + lrow[p]) * CC + lcol[p];
        }
        b_off[p] = (size_t)(n0 + lrow[p]) * CC + lcol[p];
    }

    // ---- warp decomposition: 2(m) x 4(n) warps; warp tile 64x32 ----
    const int w = tid >> 5, lane = tid & 31;
    const int wm0 = (w >> 2) * 64;            // 0 or 64
    const int wn0 = (w & 3) * 32;             // 0,32,64,96
    const int lq = lane >> 2;                 // 0..7
    const int lr = lane & 3;                  // 0..3

    float acc[4][4][4] = {};                  // [mtile][ntile][reg]

    float4 pa[2], pb[2];
    #pragma unroll
    for (int p = 0; p < 2; p++) {
        pa[p] = *(const float4*)(Ap + a_off[p]);
        pb[p] = *(const float4*)(W  + b_off[p]);
    }

    int buf = 0;
    for (int kt = 0; kt < CC / 16; kt++) {
        #pragma unroll
        for (int p = 0; p < 2; p++) {
            *(float4*)&As[buf][lrow[p]][lcol[p]] = pa[p];
            *(float4*)&Bs[buf][lrow[p]][lcol[p]] = pb[p];
        }
        __syncthreads();
        if (kt + 1 < CC / 16) {
            #pragma unroll
            for (int p = 0; p < 2; p++) {
                pa[p] = *(const float4*)(Ap + a_off[p] + (kt + 1) * 16);
                pb[p] = *(const float4*)(W  + b_off[p] + (kt + 1) * 16);
            }
        }
        #pragma unroll
        for (int kh = 0; kh < 2; kh++) {
            const int kb = kh * 8;
            uint32_t ah[4][4], al[4][4];
            #pragma unroll
            for (int i = 0; i < 4; i++) {
                const int r = wm0 + i * 16 + lq;
                split_tf32(As[buf][r    ][kb + lr    ], ah[i][0], al[i][0]);
                split_tf32(As[buf][r + 8][kb + lr    ], ah[i][1], al[i][1]);
                split_tf32(As[buf][r    ][kb + lr + 4], ah[i][2], al[i][2]);
                split_tf32(As[buf][r + 8][kb + lr + 4], ah[i][3], al[i][3]);
            }
            uint32_t bh[4][2], bl[4][2];
            #pragma unroll
            for (int j = 0; j < 4; j++) {
                const int n = wn0 + j * 8 + lq;
                split_tf32(Bs[buf][n][kb + lr    ], bh[j][0], bl[j][0]);
                split_tf32(Bs[buf][n][kb + lr + 4], bh[j][1], bl[j][1]);
            }
            #pragma unroll
            for (int i = 0; i < 4; i++)
                #pragma unroll
                for (int j = 0; j < 4; j++) {
                    mma_tf32(acc[i][j], al[i], bh[j][0], bh[j][1]);
                    uint32_t abl[4] = {ah[i][0], ah[i][1], ah[i][2], ah[i][3]};
                    mma_tf32(acc[i][j], abl, bl[j][0], bl[j][1]);
                    mma_tf32(acc[i][j], abl, bh[j][0], bh[j][1]);
                }
        }
        buf ^= 1;
    }

    // ---- epilogue ----
    #pragma unroll
    for (int i = 0; i < 4; i++) {
        #pragma unroll
        for (int half = 0; half < 2; half++) {
            const int m = m0 + wm0 + i * 16 + lq + half * 8;
            if (MODE == 1 && m >= cnt) continue;
            #pragma unroll
            for (int j = 0; j < 4; j++) {
                const int c  = n0 + wn0 + j * 8 + 2 * lr;
                const float v0 = acc[i][j][half * 2];
                const float v1 = acc[i][j][half * 2 + 1];
                if (MODE == 0) {
                    const int bpos = m >> 11, nn = m & 2047;
                    const int h = c >> 6, d = c & 63;
                    *(float2*)&g_q[(((size_t)bpos * HH + h) * NN + nn) * DD + d] =
                        make_float2(v0, v1);
                } else if (MODE == 1) {
                    const bool isv = (c >= 768);
                    const int cc2 = isv ? (c - 768) : c;
                    const int h = cc2 >> 6, d = cc2 & 63;
                    float* dst = isv ? g_v : g_k;
                    *(float2*)&dst[(((size_t)b * HH + h) * NN + m) * DD + d] =
                        make_float2(v0, v1);
                } else {
                    *(float2*)&out[(size_t)m * CC + c] =
                        make_float2(v0 + bias[c], v1 + bias[c + 1]);
                }
            }
        }
    }
}

// ---------------------------------------------------------------------------
// Flash attention with tf32 mma.sync (m16n8k8), compacted keys. (unchanged)
// ---------------------------------------------------------------------------
#define KP 68
#define VP 72

__global__ __launch_bounds__(128) void attn_kernel()
{
    extern __shared__ float sm[];
    float* Ks = sm;                  // 64 * 68
    float* Vs = Ks + 64 * KP;        // 64 * 72
    float* Ps = Vs + 64 * VP;        // 64 * 68 (16 rows per warp)

    const int tid  = threadIdx.x;
    const int w    = tid >> 5, lane = tid & 31;
    const int lq   = lane >> 2;
    const int lr   = lane & 3;
    const int q0   = blockIdx.x * 64;
    const int h    = blockIdx.y;
    const int b    = blockIdx.z;
    const int cnt  = g_cnt[b];
    const size_t base = ((size_t)(b * HH + h)) * NN * DD;
    float* Pw = Ps + w * 16 * KP;

    for (int e = tid * 4; e < 64 * 64; e += 512) {
        const int r = e >> 6, c = e & 63;
        *(float4*)(Ks + r * KP + c) =
            *(const float4*)(g_q + base + (size_t)(q0 + r) * DD + c);
    }
    __syncthreads();
    uint32_t qa[8][4];
    #pragma unroll
    for (int kc = 0; kc < 8; kc++) {
        const int r0 = w * 16 + lq;
        qa[kc][0] = to_tf32(Ks[r0 * KP + kc * 8 + lr] * 0.125f);
        qa[kc][1] = to_tf32(Ks[(r0 + 8) * KP + kc * 8 + lr] * 0.125f);
        qa[kc][2] = to_tf32(Ks[r0 * KP + kc * 8 + lr + 4] * 0.125f);
        qa[kc][3] = to_tf32(Ks[(r0 + 8) * KP + kc * 8 + lr + 4] * 0.125f);
    }

    float o[8][4] = {};
    float m0 = -1e30f, m1 = -1e30f, l0 = 0.f, l1 = 0.f;
    const float4 z4 = make_float4(0.f, 0.f, 0.f, 0.f);

    for (int kt = 0; kt < cnt; kt += 64) {
        __syncthreads();
        for (int e = tid * 4; e < 64 * 64; e += 512) {
            const int r = e >> 6, c = e & 63;
            const int gr = kt + r;
            float4 k4 = z4, v4 = z4;
            if (gr < cnt) {
                k4 = *(const float4*)(g_k + base + (size_t)gr * DD + c);
                v4 = *(const float4*)(g_v + base + (size_t)gr * DD + c);
            }
            *(float4*)(Ks + r * KP + c) = k4;
            *(float4*)(Vs + r * VP + c) = v4;
        }
        __syncthreads();

        float s[8][4];
        #pragma unroll
        for (int nt = 0; nt < 8; nt++) {
            s[nt][0] = s[nt][1] = s[nt][2] = s[nt][3] = 0.f;
            #pragma unroll
            for (int kc = 0; kc < 8; kc++) {
                const uint32_t b0 =
                    __float_as_uint(Ks[(nt * 8 + lq) * KP + kc * 8 + lr]);
                const uint32_t b1 =
                    __float_as_uint(Ks[(nt * 8 + lq) * KP + kc * 8 + lr + 4]);
                mma_tf32(s[nt], qa[kc], b0, b1);
            }
        }

        float mx0 = -1e30f, mx1 = -1e30f;
        #pragma unroll
        for (int nt = 0; nt < 8; nt++) {
            const int col = kt + nt * 8 + 2 * lr;
            if (col >= cnt)     { s[nt][0] = -1e30f; s[nt][2] = -1e30f; }
            if (col + 1 >= cnt) { s[nt][1] = -1e30f; s[nt][3] = -1e30f; }
            mx0 = fmaxf(mx0, fmaxf(s[nt][0], s[nt][1]));
            mx1 = fmaxf(mx1, fmaxf(s[nt][2], s[nt][3]));
        }
        mx0 = fmaxf(mx0, __shfl_xor_sync(0xffffffffu, mx0, 1));
        mx0 = fmaxf(mx0, __shfl_xor_sync(0xffffffffu, mx0, 2));
        mx1 = fmaxf(mx1, __shfl_xor_sync(0xffffffffu, mx1, 1));
        mx1 = fmaxf(mx1, __shfl_xor_sync(0xffffffffu, mx1, 2));
        const float mn0 = fmaxf(m0, mx0), mn1 = fmaxf(m1, mx1);
        const float al0 = __expf(m0 - mn0), al1 = __expf(m1 - mn1);
        m0 = mn0; m1 = mn1;

        float ls0 = 0.f, ls1 = 0.f;
        #pragma unroll
        for (int nt = 0; nt < 8; nt++) {
            const float p0 = __expf(s[nt][0] - mn0);
            const float p1 = __expf(s[nt][1] - mn0);
            const float p2 = __expf(s[nt][2] - mn1);
            const float p3 = __expf(s[nt][3] - mn1);
            ls0 += p0 + p1; ls1 += p2 + p3;
            const int c0 = nt * 8 + 2 * lr;
            Pw[lq * KP + c0]           = __uint_as_float(to_tf32(p0));
            Pw[lq * KP + c0 + 1]       = __uint_as_float(to_tf32(p1));
            Pw[(lq + 8) * KP + c0]     = __uint_as_float(to_tf32(p2));
            Pw[(lq + 8) * KP + c0 + 1] = __uint_as_float(to_tf32(p3));
        }
        ls0 += __shfl_xor_sync(0xffffffffu, ls0, 1);
        ls0 += __shfl_xor_sync(0xffffffffu, ls0, 2);
        ls1 += __shfl_xor_sync(0xffffffffu, ls1, 1);
        ls1 += __shfl_xor_sync(0xffffffffu, ls1, 2);
        l0 = l0 * al0 + ls0;
        l1 = l1 * al1 + ls1;
        #pragma unroll
        for (int dt = 0; dt < 8; dt++) {
            o[dt][0] *= al0; o[dt][1] *= al0;
            o[dt][2] *= al1; o[dt][3] *= al1;
        }
        __syncwarp();

        #pragma unroll
        for (int kc = 0; kc < 8; kc++) {
            uint32_t pa[4];
            pa[0] = __float_as_uint(Pw[lq * KP + kc * 8 + lr]);
            pa[1] = __float_as_uint(Pw[(lq + 8) * KP + kc * 8 + lr]);
            pa[2] = __float_as_uint(Pw[lq * KP + kc * 8 + lr + 4]);
            pa[3] = __float_as_uint(Pw[(lq + 8) * KP + kc * 8 + lr + 4]);
            #pragma unroll
            for (int dt = 0; dt < 8; dt++) {
                const uint32_t b0 =
                    __float_as_uint(Vs[(kc * 8 + lr) * VP + dt * 8 + lq]);
                const uint32_t b1 =
                    __float_as_uint(Vs[(kc * 8 + lr + 4) * VP + dt * 8 + lq]);
                mma_tf32(o[dt], pa, b0, b1);
            }
        }
        __syncwarp();
    }

    const float inv0 = 1.0f / l0, inv1 = 1.0f / l1;
    const int r0 = q0 + w * 16 + lq, r1 = r0 + 8;
    #pragma unroll
    for (int dt = 0; dt < 8; dt++) {
        const int d = h * 64 + dt * 8 + 2 * lr;
        *(float2*)(g_att + ((size_t)(b * NN + r0)) * CC + d) =
            make_float2(o[dt][0] * inv0, o[dt][1] * inv0);
        *(float2*)(g_att + ((size_t)(b * NN + r1)) * CC + d) =
            make_float2(o[dt][2] * inv1, o[dt][3] * inv1);
    }
}

// ---------------------------------------------------------------------------

extern "C" void kernel_launch(void* const* d_in, const int* in_sizes, int n_in,
                              void* d_out, int out_size)
{
    const float* x      = (const float*)d_in[0];
    const float* mask   = (const float*)d_in[1];
    const float* qkv_w  = (const float*)d_in[2];
    const float* proj_w = (const float*)d_in[3];
    const float* proj_b = (const float*)d_in[4];
    float* out = (float*)d_out;

    const int smem_attn = (64 * KP + 64 * VP + 64 * KP) * (int)sizeof(float);
    cudaFuncSetAttribute(attn_kernel,
                         cudaFuncAttributeMaxDynamicSharedMemorySize, smem_attn);

    compact_kernel<<<BB, 1024>>>(mask);
    gemm_t<0><<<dim3(CC / 128, (BB * NN) / 128), 256>>>(x, qkv_w, nullptr, nullptr);
    gemm_t<1><<<dim3(2 * CC / 128, NN / 128, BB), 256>>>(x, qkv_w + 768 * CC,
                                                         nullptr, nullptr);
    attn_kernel<<<dim3(NN / 64, HH, BB), 128, smem_attn>>>();
    gemm_t<2><<<dim3(CC / 128, (BB * NN) / 128), 256>>>(nullptr, proj_w, proj_b, out);
}

// round 7
// speedup vs baseline: 1.4799x; 1.4799x over previous
#include <cuda_runtime.h>
#include <cuda_bf16.h>
#include <cstdint>

#define BB   2
#define HH   12
#define NN   2048
#define CC   768
#define DD   64

// Scratch (no allocations allowed)
__device__ float g_q[BB*HH*NN*DD];
__device__ float g_k[BB*HH*NN*DD];
__device__ float g_v[BB*HH*NN*DD];
__device__ float g_att[BB*NN*CC];
__device__ int   g_idx[BB*NN];
__device__ int   g_cnt[BB];

// ---------------------------------------------------------------------------
// mma helpers
// ---------------------------------------------------------------------------
__device__ __forceinline__ void mma_tf32(float* d, const uint32_t* a,
                                         uint32_t b0, uint32_t b1)
{
    asm volatile(
        "mma.sync.aligned.m16n8k8.row.col.f32.tf32.tf32.f32 "
        "{%0,%1,%2,%3},{%4,%5,%6,%7},{%8,%9},{%0,%1,%2,%3};"
        : "+f"(d[0]), "+f"(d[1]), "+f"(d[2]), "+f"(d[3])
        : "r"(a[0]), "r"(a[1]), "r"(a[2]), "r"(a[3]), "r"(b0), "r"(b1));
}

__device__ __forceinline__ void mma_bf16(float* d, const uint32_t* a,
                                         uint32_t b0, uint32_t b1)
{
    asm volatile(
        "mma.sync.aligned.m16n8k16.row.col.f32.bf16.bf16.f32 "
        "{%0,%1,%2,%3},{%4,%5,%6,%7},{%8,%9},{%0,%1,%2,%3};"
        : "+f"(d[0]), "+f"(d[1]), "+f"(d[2]), "+f"(d[3])
        : "r"(a[0]), "r"(a[1]), "r"(a[2]), "r"(a[3]), "r"(b0), "r"(b1));
}

__device__ __forceinline__ uint32_t to_tf32(float f)
{
    uint32_t u;
    asm("cvt.rna.tf32.f32 %0, %1;" : "=r"(u) : "f"(f));
    return u;
}

// split pair (x,y) into packed-bf16 hi word + lo (residual) word
__device__ __forceinline__ void cvt_pair(float x, float y,
                                         uint32_t& hi, uint32_t& lo)
{
    const __nv_bfloat16 hx = __float2bfloat16(x);
    const __nv_bfloat16 hy = __float2bfloat16(y);
    __nv_bfloat162 h; h.x = hx; h.y = hy;
    hi = *reinterpret_cast<uint32_t*>(&h);
    __nv_bfloat162 l;
    l.x = __float2bfloat16(x - __bfloat162float(hx));
    l.y = __float2bfloat16(y - __bfloat162float(hy));
    lo = *reinterpret_cast<uint32_t*>(&l);
}

// ---------------------------------------------------------------------------
// Compaction: per batch, gather indices of visible keys (mask == 0).
// ---------------------------------------------------------------------------
__global__ __launch_bounds__(1024) void compact_kernel(const float* __restrict__ mask)
{
    __shared__ int wsum[32];
    const int b = blockIdx.x;
    const int t = threadIdx.x;
    const int p0 = 2 * t, p1 = 2 * t + 1;
    const int v0 = (mask[b * NN + p0] == 0.0f) ? 1 : 0;
    const int v1 = (mask[b * NN + p1] == 0.0f) ? 1 : 0;
    const int s  = v0 + v1;

    int sc = s;
    #pragma unroll
    for (int o = 1; o < 32; o <<= 1) {
        int n = __shfl_up_sync(0xffffffffu, sc, o);
        if ((t & 31) >= o) sc += n;
    }
    if ((t & 31) == 31) wsum[t >> 5] = sc;
    __syncthreads();
    if (t < 32) {
        int w = wsum[t];
        #pragma unroll
        for (int o = 1; o < 32; o <<= 1) {
            int n = __shfl_up_sync(0xffffffffu, w, o);
            if (t >= o) w += n;
        }
        wsum[t] = w;
    }
    __syncthreads();
    const int excl = (sc - s) + ((t >= 32) ? wsum[(t >> 5) - 1] : 0);
    if (v0) g_idx[b * NN + excl] = p0;
    if (v1) g_idx[b * NN + excl + v0] = p1;
    if (t == 1023) g_cnt[b] = excl + s;
}

// ---------------------------------------------------------------------------
// Tensor-core GEMM, 3xBF16 split (error ~2^-16, negligible here).
// C[m,n] = sum_k A[m,k] * W[n,k]
// Block tile 128x128, k-step 32, double-buffered dynamic smem (hi/lo bf16
// pair-words == mma fragment registers), 8 warps (64x32 each).
// MODE 0: Q proj -> g_q   MODE 1: K/V proj (compacted) -> g_k/g_v
// MODE 2: out proj (+bias) -> out
// ---------------------------------------------------------------------------
#define GP 20              // smem pitch in 32-bit words (16 used)
#define BUFW (4*128*GP)    // words per buffer (AH, AL, BH, BL)

template<int MODE>
__global__ __launch_bounds__(256) void gemm_b(const float* __restrict__ A,
                                              const float* __restrict__ W,
                                              const float* __restrict__ bias,
                                              float* __restrict__ out)
{
    extern __shared__ uint32_t su[];

    const int tid = threadIdx.x;
    const int n0 = blockIdx.x * 128;
    const int m0 = blockIdx.y * 128;
    int b = 0, cnt = 0;
    if (MODE == 1) {
        b = blockIdx.z;
        cnt = g_cnt[b];
        if (m0 >= cnt) return;
    }
    const float* Ap = (MODE == 2) ? g_att : A;

    // ---- loader mapping: 4 float4 per matrix per thread (128 x 32 floats) ----
    int lrow[4], lw[4];
    size_t a_off[4], b_off[4];
    #pragma unroll
    for (int p = 0; p < 4; p++) {
        const int f = tid + p * 256;         // 0..1023
        lrow[p] = f >> 3;                    // 0..127
        lw[p]   = (f & 7) * 2;               // word index 0,2,..,14
        const int col4 = (f & 7) * 4;
        if (MODE == 1) {
            const int mrow = m0 + lrow[p];
            const int src  = (mrow < cnt) ? g_idx[b * NN + mrow] : 0;
            a_off[p] = ((size_t)(b * NN + src)) * CC + col4;
        } else {
            a_off[p] = (size_t)(m0 + lrow[p]) * CC + col4;
        }
        b_off[p] = (size_t)(n0 + lrow[p]) * CC + col4;
    }

    // ---- warp decomposition: 2(m) x 4(n) warps; warp tile 64x32 ----
    const int w = tid >> 5, lane = tid & 31;
    const int wm0 = (w >> 2) * 64;
    const int wn0 = (w & 3) * 32;
    const int lq = lane >> 2;                // 0..7
    const int lr = lane & 3;                 // 0..3

    float acc[4][4][4] = {};

    float4 pa[4], pb[4];
    #pragma unroll
    for (int p = 0; p < 4; p++) {
        pa[p] = *(const float4*)(Ap + a_off[p]);
        pb[p] = *(const float4*)(W  + b_off[p]);
    }

    int buf = 0;
    const int NK = CC / 32;                  // 24
    for (int kt = 0; kt < NK; kt++) {
        uint32_t* AH = su + buf * BUFW;
        uint32_t* AL = AH + 128 * GP;
        uint32_t* BH = AL + 128 * GP;
        uint32_t* BL = BH + 128 * GP;

        #pragma unroll
        for (int p = 0; p < 4; p++) {
            uint32_t h0, l0, h1, l1;
            cvt_pair(pa[p].x, pa[p].y, h0, l0);
            cvt_pair(pa[p].z, pa[p].w, h1, l1);
            *(uint2*)&AH[lrow[p] * GP + lw[p]] = make_uint2(h0, h1);
            *(uint2*)&AL[lrow[p] * GP + lw[p]] = make_uint2(l0, l1);
            cvt_pair(pb[p].x, pb[p].y, h0, l0);
            cvt_pair(pb[p].z, pb[p].w, h1, l1);
            *(uint2*)&BH[lrow[p] * GP + lw[p]] = make_uint2(h0, h1);
            *(uint2*)&BL[lrow[p] * GP + lw[p]] = make_uint2(l0, l1);
        }
        __syncthreads();

        if (kt + 1 < NK) {
            #pragma unroll
            for (int p = 0; p < 4; p++) {
                pa[p] = *(const float4*)(Ap + a_off[p] + (kt + 1) * 32);
                pb[p] = *(const float4*)(W  + b_off[p] + (kt + 1) * 32);
            }
        }

        #pragma unroll
        for (int kb = 0; kb < 2; kb++) {
            const int wb = kb * 8;
            uint32_t aH[4][4], aL[4][4];
            #pragma unroll
            for (int i = 0; i < 4; i++) {
                const int r = wm0 + i * 16 + lq;
                aH[i][0] = AH[r * GP + wb + lr];
                aH[i][1] = AH[(r + 8) * GP + wb + lr];
                aH[i][2] = AH[r * GP + wb + 4 + lr];
                aH[i][3] = AH[(r + 8) * GP + wb + 4 + lr];
                aL[i][0] = AL[r * GP + wb + lr];
                aL[i][1] = AL[(r + 8) * GP + wb + lr];
                aL[i][2] = AL[r * GP + wb + 4 + lr];
                aL[i][3] = AL[(r + 8) * GP + wb + 4 + lr];
            }
            uint32_t bH[4][2], bL[4][2];
            #pragma unroll
            for (int j = 0; j < 4; j++) {
                const int n = wn0 + j * 8 + lq;
                bH[j][0] = BH[n * GP + wb + lr];
                bH[j][1] = BH[n * GP + wb + 4 + lr];
                bL[j][0] = BL[n * GP + wb + lr];
                bL[j][1] = BL[n * GP + wb + 4 + lr];
            }
            #pragma unroll
            for (int i = 0; i < 4; i++)
                #pragma unroll
                for (int j = 0; j < 4; j++) {
                    mma_bf16(acc[i][j], aH[i], bH[j][0], bH[j][1]);
                    mma_bf16(acc[i][j], aH[i], bL[j][0], bL[j][1]);
                    mma_bf16(acc[i][j], aL[i], bH[j][0], bH[j][1]);
                }
        }
        __syncthreads();
        buf ^= 1;
    }

    // ---- epilogue ----
    #pragma unroll
    for (int i = 0; i < 4; i++) {
        #pragma unroll
        for (int half = 0; half < 2; half++) {
            const int m = m0 + wm0 + i * 16 + lq + half * 8;
            if (MODE == 1 && m >= cnt) continue;
            #pragma unroll
            for (int j = 0; j < 4; j++) {
                const int c  = n0 + wn0 + j * 8 + 2 * lr;
                const float v0 = acc[i][j][half * 2];
                const float v1 = acc[i][j][half * 2 + 1];
                if (MODE == 0) {
                    const int bpos = m >> 11, nn = m & 2047;
                    const int h = c >> 6, d = c & 63;
                    *(float2*)&g_q[(((size_t)bpos * HH + h) * NN + nn) * DD + d] =
                        make_float2(v0, v1);
                } else if (MODE == 1) {
                    const bool isv = (c >= 768);
                    const int cc2 = isv ? (c - 768) : c;
                    const int h = cc2 >> 6, d = cc2 & 63;
                    float* dst = isv ? g_v : g_k;
                    *(float2*)&dst[(((size_t)b * HH + h) * NN + m) * DD + d] =
                        make_float2(v0, v1);
                } else {
                    *(float2*)&out[(size_t)m * CC + c] =
                        make_float2(v0 + bias[c], v1 + bias[c + 1]);
                }
            }
        }
    }
}

// ---------------------------------------------------------------------------
// Flash attention with tf32 mma.sync (m16n8k8), compacted keys. (unchanged)
// ---------------------------------------------------------------------------
#define KP 68
#define VP 72

__global__ __launch_bounds__(128) void attn_kernel()
{
    extern __shared__ float sm[];
    float* Ks = sm;
    float* Vs = Ks + 64 * KP;
    float* Ps = Vs + 64 * VP;

    const int tid  = threadIdx.x;
    const int w    = tid >> 5, lane = tid & 31;
    const int lq   = lane >> 2;
    const int lr   = lane & 3;
    const int q0   = blockIdx.x * 64;
    const int h    = blockIdx.y;
    const int b    = blockIdx.z;
    const int cnt  = g_cnt[b];
    const size_t base = ((size_t)(b * HH + h)) * NN * DD;
    float* Pw = Ps + w * 16 * KP;

    for (int e = tid * 4; e < 64 * 64; e += 512) {
        const int r = e >> 6, c = e & 63;
        *(float4*)(Ks + r * KP + c) =
            *(const float4*)(g_q + base + (size_t)(q0 + r) * DD + c);
    }
    __syncthreads();
    uint32_t qa[8][4];
    #pragma unroll
    for (int kc = 0; kc < 8; kc++) {
        const int r0 = w * 16 + lq;
        qa[kc][0] = to_tf32(Ks[r0 * KP + kc * 8 + lr] * 0.125f);
        qa[kc][1] = to_tf32(Ks[(r0 + 8) * KP + kc * 8 + lr] * 0.125f);
        qa[kc][2] = to_tf32(Ks[r0 * KP + kc * 8 + lr + 4] * 0.125f);
        qa[kc][3] = to_tf32(Ks[(r0 + 8) * KP + kc * 8 + lr + 4] * 0.125f);
    }

    float o[8][4] = {};
    float m0 = -1e30f, m1 = -1e30f, l0 = 0.f, l1 = 0.f;
    const float4 z4 = make_float4(0.f, 0.f, 0.f, 0.f);

    for (int kt = 0; kt < cnt; kt += 64) {
        __syncthreads();
        for (int e = tid * 4; e < 64 * 64; e += 512) {
            const int r = e >> 6, c = e & 63;
            const int gr = kt + r;
            float4 k4 = z4, v4 = z4;
            if (gr < cnt) {
                k4 = *(const float4*)(g_k + base + (size_t)gr * DD + c);
                v4 = *(const float4*)(g_v + base + (size_t)gr * DD + c);
            }
            *(float4*)(Ks + r * KP + c) = k4;
            *(float4*)(Vs + r * VP + c) = v4;
        }
        __syncthreads();

        float s[8][4];
        #pragma unroll
        for (int nt = 0; nt < 8; nt++) {
            s[nt][0] = s[nt][1] = s[nt][2] = s[nt][3] = 0.f;
            #pragma unroll
            for (int kc = 0; kc < 8; kc++) {
                const uint32_t b0 =
                    __float_as_uint(Ks[(nt * 8 + lq) * KP + kc * 8 + lr]);
                const uint32_t b1 =
                    __float_as_uint(Ks[(nt * 8 + lq) * KP + kc * 8 + lr + 4]);
                mma_tf32(s[nt], qa[kc], b0, b1);
            }
        }

        float mx0 = -1e30f, mx1 = -1e30f;
        #pragma unroll
        for (int nt = 0; nt < 8; nt++) {
            const int col = kt + nt * 8 + 2 * lr;
            if (col >= cnt)     { s[nt][0] = -1e30f; s[nt][2] = -1e30f; }
            if (col + 1 >= cnt) { s[nt][1] = -1e30f; s[nt][3] = -1e30f; }
            mx0 = fmaxf(mx0, fmaxf(s[nt][0], s[nt][1]));
            mx1 = fmaxf(mx1, fmaxf(s[nt][2], s[nt][3]));
        }
        mx0 = fmaxf(mx0, __shfl_xor_sync(0xffffffffu, mx0, 1));
        mx0 = fmaxf(mx0, __shfl_xor_sync(0xffffffffu, mx0, 2));
        mx1 = fmaxf(mx1, __shfl_xor_sync(0xffffffffu, mx1, 1));
        mx1 = fmaxf(mx1, __shfl_xor_sync(0xffffffffu, mx1, 2));
        const float mn0 = fmaxf(m0, mx0), mn1 = fmaxf(m1, mx1);
        const float al0 = __expf(m0 - mn0), al1 = __expf(m1 - mn1);
        m0 = mn0; m1 = mn1;

        float ls0 = 0.f, ls1 = 0.f;
        #pragma unroll
        for (int nt = 0; nt < 8; nt++) {
            const float p0 = __expf(s[nt][0] - mn0);
            const float p1 = __expf(s[nt][1] - mn0);
            const float p2 = __expf(s[nt][2] - mn1);
            const float p3 = __expf(s[nt][3] - mn1);
            ls0 += p0 + p1; ls1 += p2 + p3;
            const int c0 = nt * 8 + 2 * lr;
            Pw[lq * KP + c0]           = __uint_as_float(to_tf32(p0));
            Pw[lq * KP + c0 + 1]       = __uint_as_float(to_tf32(p1));
            Pw[(lq + 8) * KP + c0]     = __uint_as_float(to_tf32(p2));
            Pw[(lq + 8) * KP + c0 + 1] = __uint_as_float(to_tf32(p3));
        }
        ls0 += __shfl_xor_sync(0xffffffffu, ls0, 1);
        ls0 += __shfl_xor_sync(0xffffffffu, ls0, 2);
        ls1 += __shfl_xor_sync(0xffffffffu, ls1, 1);
        ls1 += __shfl_xor_sync(0xffffffffu, ls1, 2);
        l0 = l0 * al0 + ls0;
        l1 = l1 * al1 + ls1;
        #pragma unroll
        for (int dt = 0; dt < 8; dt++) {
            o[dt][0] *= al0; o[dt][1] *= al0;
            o[dt][2] *= al1; o[dt][3] *= al1;
        }
        __syncwarp();

        #pragma unroll
        for (int kc = 0; kc < 8; kc++) {
            uint32_t pa[4];
            pa[0] = __float_as_uint(Pw[lq * KP + kc * 8 + lr]);
            pa[1] = __float_as_uint(Pw[(lq + 8) * KP + kc * 8 + lr]);
            pa[2] = __float_as_uint(Pw[lq * KP + kc * 8 + lr + 4]);
            pa[3] = __float_as_uint(Pw[(lq + 8) * KP + kc * 8 + lr + 4]);
            #pragma unroll
            for (int dt = 0; dt < 8; dt++) {
                const uint32_t b0 =
                    __float_as_uint(Vs[(kc * 8 + lr) * VP + dt * 8 + lq]);
                const uint32_t b1 =
                    __float_as_uint(Vs[(kc * 8 + lr + 4) * VP + dt * 8 + lq]);
                mma_tf32(o[dt], pa, b0, b1);
            }
        }
        __syncwarp();
    }

    const float inv0 = 1.0f / l0, inv1 = 1.0f / l1;
    const int r0 = q0 + w * 16 + lq, r1 = r0 + 8;
    #pragma unroll
    for (int dt = 0; dt < 8; dt++) {
        const int d = h * 64 + dt * 8 + 2 * lr;
        *(float2*)(g_att + ((size_t)(b * NN + r0)) * CC + d) =
            make_float2(o[dt][0] * inv0, o[dt][1] * inv0);
        *(float2*)(g_att + ((size_t)(b * NN + r1)) * CC + d) =
            make_float2(o[dt][2] * inv1, o[dt][3] * inv1);
    }
}

// ---------------------------------------------------------------------------

extern "C" void kernel_launch(void* const* d_in, const int* in_sizes, int n_in,
                              void* d_out, int out_size)
{
    const float* x      = (const float*)d_in[0];
    const float* mask   = (const float*)d_in[1];
    const float* qkv_w  = (const float*)d_in[2];
    const float* proj_w = (const float*)d_in[3];
    const float* proj_b = (const float*)d_in[4];
    float* out = (float*)d_out;

    const int smem_attn = (64 * KP + 64 * VP + 64 * KP) * (int)sizeof(float);
    cudaFuncSetAttribute(attn_kernel,
                         cudaFuncAttributeMaxDynamicSharedMemorySize, smem_attn);

    const int smem_gemm = 2 * BUFW * (int)sizeof(uint32_t);   // 81,920 B
    cudaFuncSetAttribute(gemm_b<0>,
                         cudaFuncAttributeMaxDynamicSharedMemorySize, smem_gemm);
    cudaFuncSetAttribute(gemm_b<1>,
                         cudaFuncAttributeMaxDynamicSharedMemorySize, smem_gemm);
    cudaFuncSetAttribute(gemm_b<2>,
                         cudaFuncAttributeMaxDynamicSharedMemorySize, smem_gemm);

    compact_kernel<<<BB, 1024>>>(mask);
    gemm_b<0><<<dim3(CC / 128, (BB * NN) / 128), 256, smem_gemm>>>(
        x, qkv_w, nullptr, nullptr);
    gemm_b<1><<<dim3(2 * CC / 128, NN / 128, BB), 256, smem_gemm>>>(
        x, qkv_w + 768 * CC, nullptr, nullptr);
    attn_kernel<<<dim3(NN / 64, HH, BB), 128, smem_attn>>>();
    gemm_b<2><<<dim3(CC / 128, (BB * NN) / 128), 256, smem_gemm>>>(
        nullptr, proj_w, proj_b, out);
}